// round 1
// baseline (speedup 1.0000x reference)
#include <cuda_runtime.h>
#include <cstdint>

// ---------------------------------------------------------------------------
// Gate_32375463478041
//   x:       [32, 4096, 128, 2] f32   (row = batch*128 + channel, K = seq*2)
//   W_main:  [64, 8192] f32,  b_main: [64]
//   W_noise: [64, 8192] f32,  b_noise: [64]
//   out:     [4096, 64] f32 = softmax(keep_top2(x@Wm^T + bm + softplus(x@Wn^T + bn)))
//
// Stage 1: fused fp32 GEMM (both weight mats, BN=128) using packed fma.rn.f32x2
//          (pairs packed along K), BM=128 rows (= one batch, contiguous x tiles),
//          K split 4-way across CTAs -> 128 CTAs, partials to __device__ scratch.
// Stage 2: reduce partials + bias + softplus + top-2 + softmax, warp per row.
// ---------------------------------------------------------------------------

#define KSPLIT 4
#define ROWS   4096
#define NBN    128          // 64 main + 64 noise outputs
#define KP     16           // k-pairs per chunk (KB = 32 floats)
#define NCHUNK 64           // 2048 floats of K per CTA / 32 per chunk
#define WPAD   130          // padded W smem row (float2 units), 16B-aligned stride

typedef unsigned long long ull;

__device__ float g_partial[KSPLIT * ROWS * NBN];   // 8 MiB scratch (static: allowed)

__device__ __forceinline__ void fma2(ull& d, ull a, ull b) {
    asm("fma.rn.f32x2 %0, %1, %2, %0;" : "+l"(d) : "l"(a), "l"(b));
}

__device__ __forceinline__ float pair_sum(ull v) {
    float lo = __uint_as_float((unsigned)(v & 0xffffffffull));
    float hi = __uint_as_float((unsigned)(v >> 32));
    return lo + hi;
}

// smem: Xs[2][KP][128] float2 (32768B) then Ws[2][KP][WPAD] float2 (33280B)
#define SMEM_BYTES (2*KP*128*8 + 2*KP*WPAD*8)

__global__ void __launch_bounds__(256, 1) gate_gemm_kernel(
    const float* __restrict__ x,
    const float* __restrict__ Wm,
    const float* __restrict__ Wn)
{
    extern __shared__ char smem[];
    float2* Xs = (float2*)smem;                       // [2][KP][128]
    float2* Ws = (float2*)(smem + 2*KP*128*8);        // [2][KP][WPAD]

    const int b  = blockIdx.x;        // batch -> rows b*128 .. b*128+127
    const int ks = blockIdx.y;        // k-split slice
    const int t  = threadIdx.x;       // 256 threads
    const int tx = t & 15;            // n-tile:  n = tx*4 + u  (+64 for noise)
    const int ty = t >> 4;            // m-tile:  m = ty*8 + mi

    // ---- global pointers -------------------------------------------------
    // x chunk c: contiguous 16KB at x + b*1048576 + (ks*1024 + c*16)*256
    const float4* xg = (const float4*)(x + (size_t)b * 1048576u + (size_t)ks * 262144u);

    // W: thread loads float4 i = t + 256*r  ->  n = t/8 + 32r, j = t&7 (const)
    const int j = t & 7;
    const float* wrow[4];
#pragma unroll
    for (int r = 0; r < 4; r++) {
        int n = (t >> 3) + 32 * r;
        const float* base = (n < 64) ? (Wm + (size_t)n * 8192u)
                                     : (Wn + (size_t)(n - 64) * 8192u);
        wrow[r] = base + ks * 2048 + j * 4;
    }

    ull acc[8][8];
#pragma unroll
    for (int i = 0; i < 8; i++)
#pragma unroll
        for (int k = 0; k < 8; k++) acc[i][k] = 0ull;

    float4 xstage[4], wstage[4];

    // ---- prologue: load + store chunk 0 -----------------------------------
    {
        const float4* xp = xg;   // chunk 0
#pragma unroll
        for (int r = 0; r < 4; r++) xstage[r] = xp[t + 256 * r];
#pragma unroll
        for (int r = 0; r < 4; r++) wstage[r] = *(const float4*)(wrow[r]);

        float4* xsb = (float4*)Xs;      // buffer 0
#pragma unroll
        for (int r = 0; r < 4; r++) xsb[t + 256 * r] = xstage[r];
        float2* wsb = Ws;               // buffer 0
#pragma unroll
        for (int r = 0; r < 4; r++) {
            int n = (t >> 3) + 32 * r;
            wsb[(2 * j)     * WPAD + n] = make_float2(wstage[r].x, wstage[r].y);
            wsb[(2 * j + 1) * WPAD + n] = make_float2(wstage[r].z, wstage[r].w);
        }
    }
    __syncthreads();

    // ---- main loop ---------------------------------------------------------
    for (int c = 0; c < NCHUNK; c++) {
        const int buf = c & 1;

        if (c + 1 < NCHUNK) {
            const float4* xp = xg + (size_t)(c + 1) * 1024u;
#pragma unroll
            for (int r = 0; r < 4; r++) xstage[r] = xp[t + 256 * r];
#pragma unroll
            for (int r = 0; r < 4; r++) wstage[r] = *(const float4*)(wrow[r] + (c + 1) * 32);
        }

        const ull* Xb = (const ull*)(Xs + buf * KP * 128);
        const ull* Wb = (const ull*)(Ws + buf * KP * WPAD);

#pragma unroll
        for (int kp = 0; kp < KP; kp++) {
            const ull* xr = Xb + kp * 128  + ty * 8;
            const ull* wr = Wb + kp * WPAD + tx * 4;

            ulonglong2 a0 = *(const ulonglong2*)(xr + 0);
            ulonglong2 a1 = *(const ulonglong2*)(xr + 2);
            ulonglong2 a2 = *(const ulonglong2*)(xr + 4);
            ulonglong2 a3 = *(const ulonglong2*)(xr + 6);
            ulonglong2 w0 = *(const ulonglong2*)(wr + 0);
            ulonglong2 w1 = *(const ulonglong2*)(wr + 2);
            ulonglong2 w2 = *(const ulonglong2*)(wr + 64);
            ulonglong2 w3 = *(const ulonglong2*)(wr + 66);

            ull av[8] = {a0.x, a0.y, a1.x, a1.y, a2.x, a2.y, a3.x, a3.y};
            ull wv[8] = {w0.x, w0.y, w1.x, w1.y, w2.x, w2.y, w3.x, w3.y};

#pragma unroll
            for (int mi = 0; mi < 8; mi++)
#pragma unroll
                for (int nj = 0; nj < 8; nj++)
                    fma2(acc[mi][nj], av[mi], wv[nj]);
        }

        if (c + 1 < NCHUNK) {
            const int nb = (c + 1) & 1;
            float4* xsb = (float4*)(Xs + nb * KP * 128);
#pragma unroll
            for (int r = 0; r < 4; r++) xsb[t + 256 * r] = xstage[r];
            float2* wsb = Ws + nb * KP * WPAD;
#pragma unroll
            for (int r = 0; r < 4; r++) {
                int n = (t >> 3) + 32 * r;
                wsb[(2 * j)     * WPAD + n] = make_float2(wstage[r].x, wstage[r].y);
                wsb[(2 * j + 1) * WPAD + n] = make_float2(wstage[r].z, wstage[r].w);
            }
        }
        __syncthreads();
    }

    // ---- write partials ----------------------------------------------------
#pragma unroll
    for (int mi = 0; mi < 8; mi++) {
        int row = b * 128 + ty * 8 + mi;
        float* pg = g_partial + ((size_t)ks * ROWS + row) * NBN + tx * 4;
        float4 o0, o1;
        o0.x = pair_sum(acc[mi][0]); o0.y = pair_sum(acc[mi][1]);
        o0.z = pair_sum(acc[mi][2]); o0.w = pair_sum(acc[mi][3]);
        o1.x = pair_sum(acc[mi][4]); o1.y = pair_sum(acc[mi][5]);
        o1.z = pair_sum(acc[mi][6]); o1.w = pair_sum(acc[mi][7]);
        *(float4*)(pg)      = o0;
        *(float4*)(pg + 64) = o1;
    }
}

// ---------------------------------------------------------------------------
// Stage 2: warp per row. lane handles experts {lane, lane+32}.
// ---------------------------------------------------------------------------
__device__ __forceinline__ float softplus_f(float v) {
    return fmaxf(v, 0.0f) + log1pf(expf(-fabsf(v)));
}

__global__ void __launch_bounds__(256) gate_epilogue_kernel(
    const float* __restrict__ bm,
    const float* __restrict__ bn,
    float* __restrict__ out)
{
    int gwarp = (blockIdx.x * blockDim.x + threadIdx.x) >> 5;
    int lane  = threadIdx.x & 31;
    if (gwarp >= ROWS) return;
    const int row = gwarp;

    float pm0 = 0.f, pm1 = 0.f, pn0 = 0.f, pn1 = 0.f;
    const float* base = g_partial + (size_t)row * NBN;
#pragma unroll
    for (int ks = 0; ks < KSPLIT; ks++) {
        const float* p = base + (size_t)ks * ROWS * NBN;
        pm0 += p[lane];      pm1 += p[lane + 32];
        pn0 += p[lane + 64]; pn1 += p[lane + 96];
    }

    float g0 = (pm0 + bm[lane])      + softplus_f(pn0 + bn[lane]);
    float g1 = (pm1 + bm[lane + 32]) + softplus_f(pn1 + bn[lane + 32]);

    // ---- top-1 ----
    float v1 = g0; int i1 = lane;
    if (g1 > v1) { v1 = g1; i1 = lane + 32; }
#pragma unroll
    for (int m = 16; m; m >>= 1) {
        float ov = __shfl_xor_sync(0xffffffffu, v1, m);
        int   oi = __shfl_xor_sync(0xffffffffu, i1, m);
        if (ov > v1 || (ov == v1 && oi < i1)) { v1 = ov; i1 = oi; }
    }

    // ---- top-2 (mask out i1) ----
    float va = (lane      == i1) ? -3.0e38f : g0;
    float vb = (lane + 32 == i1) ? -3.0e38f : g1;
    float v2 = va; int i2 = lane;
    if (vb > v2) { v2 = vb; i2 = lane + 32; }
#pragma unroll
    for (int m = 16; m; m >>= 1) {
        float ov = __shfl_xor_sync(0xffffffffu, v2, m);
        int   oi = __shfl_xor_sync(0xffffffffu, i2, m);
        if (ov > v2 || (ov == v2 && oi < i2)) { v2 = ov; i2 = oi; }
    }

    float ed = expf(v2 - v1);            // <= 1
    float p1 = 1.0f / (1.0f + ed);
    float p2 = ed / (1.0f + ed);

    float o0 = (lane      == i1) ? p1 : (lane      == i2) ? p2 : 0.0f;
    float o1 = (lane + 32 == i1) ? p1 : (lane + 32 == i2) ? p2 : 0.0f;
    out[(size_t)row * 64 + lane]      = o0;
    out[(size_t)row * 64 + lane + 32] = o1;
}

extern "C" void kernel_launch(void* const* d_in, const int* in_sizes, int n_in,
                              void* d_out, int out_size)
{
    (void)in_sizes; (void)n_in; (void)out_size;
    const float* x  = (const float*)d_in[0];
    const float* Wm = (const float*)d_in[1];
    const float* bm = (const float*)d_in[2];
    const float* Wn = (const float*)d_in[3];
    const float* bn = (const float*)d_in[4];
    float* out = (float*)d_out;

    cudaFuncSetAttribute(gate_gemm_kernel,
                         cudaFuncAttributeMaxDynamicSharedMemorySize, SMEM_BYTES);

    dim3 grid(32, KSPLIT);
    gate_gemm_kernel<<<grid, 256, SMEM_BYTES>>>(x, Wm, Wn);
    gate_epilogue_kernel<<<512, 256>>>(bm, bn, out);
}

// round 3
// speedup vs baseline: 2.2414x; 2.2414x over previous
#include <cuda_runtime.h>
#include <cstdint>

// ---------------------------------------------------------------------------
// Gate_32375463478041 — bf16x3 split GEMM on mma.sync (HMMA.16816)
//   logits[4096,128] = x_r[4096,8192] @ [Wm;Wn]^T  via 3-pass bf16 split:
//      x = xh + xl, W = wh + wl  (bf16 hi + bf16 residual)
//      x*W ~= xh*wh + xh*wl + xl*wh       (drop xl*wl ~ 2^-18)
//   CTA tile: M=128 (one batch), N=128 (64 main + 64 noise), K-split 4 -> 128 CTAs.
//   Warps 0-3: MMA (64x64 warp tiles).  Warps 4-7: producers (LDG->split->STS).
//   Chunk KB=32 k-floats; smem row = 128B = [32 hi bf16 | 32 lo bf16], SW128 swizzle.
//   Stage 2: reduce k-split partials + bias + softplus + top-2 + softmax.
// ---------------------------------------------------------------------------

#define KSPLIT 4
#define ROWS   4096
#define NCHUNK 64
#define TILE_B 16384            // 128 rows x 128B
#define STAGE_B (2*TILE_B)      // A tile + B tile
#define SMEM_BYTES (2*STAGE_B)  // double buffered: 64 KiB

__device__ float g_partial[KSPLIT * ROWS * 128];   // 8 MiB scratch

__device__ __forceinline__ uint32_t smem_u32(const void* p) {
    uint32_t a;
    asm("{ .reg .u64 t; cvta.to.shared.u64 t, %1; cvt.u32.u64 %0, t; }"
        : "=r"(a) : "l"(p));
    return a;
}

__device__ __forceinline__ void ldsm4(uint32_t* r, uint32_t addr) {
    asm volatile("ldmatrix.sync.aligned.m8n8.x4.shared.b16 {%0,%1,%2,%3}, [%4];"
                 : "=r"(r[0]), "=r"(r[1]), "=r"(r[2]), "=r"(r[3]) : "r"(addr));
}

__device__ __forceinline__ void mma16816(float* d, const uint32_t* a, const uint32_t* b) {
    asm volatile(
        "mma.sync.aligned.m16n8k16.row.col.f32.bf16.bf16.f32 "
        "{%0,%1,%2,%3}, {%4,%5,%6,%7}, {%8,%9}, {%0,%1,%2,%3};"
        : "+f"(d[0]), "+f"(d[1]), "+f"(d[2]), "+f"(d[3])
        : "r"(a[0]), "r"(a[1]), "r"(a[2]), "r"(a[3]), "r"(b[0]), "r"(b[1]));
}

// split two fp32 (f0 = even k, f1 = odd k) into packed bf16x2 hi + residual lo
__device__ __forceinline__ void split2(float f0, float f1, uint32_t& h, uint32_t& lo) {
    asm("cvt.rn.bf16x2.f32 %0, %1, %2;" : "=r"(h) : "f"(f1), "f"(f0));
    float r0 = f0 - __uint_as_float(h << 16);
    float r1 = f1 - __uint_as_float(h & 0xffff0000u);
    asm("cvt.rn.bf16x2.f32 %0, %1, %2;" : "=r"(lo) : "f"(r1), "f"(r0));
}

// ---------------------------------------------------------------------------
__global__ void __launch_bounds__(256, 1) gate_gemm_hmma(
    const float* __restrict__ x,
    const float* __restrict__ Wm,
    const float* __restrict__ Wn)
{
    extern __shared__ char smem[];
    const uint32_t sbase = smem_u32(smem);
    const int t = threadIdx.x;
    const int w = t >> 5;
    const int l = t & 31;
    const int b  = blockIdx.x;
    const int ks = blockIdx.y;

    if (w < 4) {
        // =================== MMA warps (0-3): 64x64 tile =====================
        const int wm = w & 1;           // M half
        const int wn = w >> 1;          // N half

        // per-lane ldmatrix address components
        const int m_add = ((l >> 3) & 1) * 8 + (l & 7);
        const int kA2   = (l >> 4) * 16;          // k byte offset (A)
        const int xm    = (m_add & 7) * 16;
        const int n_add = (l & 7) + ((l >> 4) << 3);
        const int kB2   = ((l >> 3) & 1) * 16;    // k byte offset (B)
        const int xn    = (n_add & 7) * 16;

        uint32_t aRow[4], bRow[4];
#pragma unroll
        for (int i = 0; i < 4; i++) {
            aRow[i] = (uint32_t)(wm * 64 + i * 16 + m_add) * 128u;
            bRow[i] = (uint32_t)(wn * 64 + i * 16 + n_add) * 128u + TILE_B;
        }

        float acc[4][8][4];
#pragma unroll
        for (int i = 0; i < 4; i++)
#pragma unroll
            for (int j = 0; j < 8; j++)
#pragma unroll
                for (int q = 0; q < 4; q++) acc[i][j][q] = 0.0f;

        __syncthreads();   // wait for prologue fill of buffer 0

        for (int c = 0; c < NCHUNK; c++) {
            const uint32_t sb = sbase + (uint32_t)(c & 1) * STAGE_B;
            uint32_t AH[16], AL[16], BH[16], BL[16];
#pragma unroll
            for (int kk = 0; kk < 2; kk++) {
                const int koH = kk * 32;
#pragma unroll
                for (int mt = 0; mt < 4; mt++) {
                    ldsm4(AH + 4 * mt, sb + aRow[mt] + ((koH      + kA2) ^ xm));
                    ldsm4(AL + 4 * mt, sb + aRow[mt] + ((64 + koH + kA2) ^ xm));
                }
#pragma unroll
                for (int nt = 0; nt < 4; nt++) {
                    ldsm4(BH + 4 * nt, sb + bRow[nt] + ((koH      + kB2) ^ xn));
                    ldsm4(BL + 4 * nt, sb + bRow[nt] + ((64 + koH + kB2) ^ xn));
                }
#pragma unroll
                for (int mt = 0; mt < 4; mt++)
#pragma unroll
                    for (int nj = 0; nj < 8; nj++)
                        mma16816(acc[mt][nj], AH + 4 * mt, BH + 2 * nj);
#pragma unroll
                for (int mt = 0; mt < 4; mt++)
#pragma unroll
                    for (int nj = 0; nj < 8; nj++)
                        mma16816(acc[mt][nj], AH + 4 * mt, BL + 2 * nj);
#pragma unroll
                for (int mt = 0; mt < 4; mt++)
#pragma unroll
                    for (int nj = 0; nj < 8; nj++)
                        mma16816(acc[mt][nj], AL + 4 * mt, BH + 2 * nj);
            }
            __syncthreads();
        }

        // ---- write partials: frag (c0,c1)@(row,col), (c2,c3)@(row+8,col) ----
#pragma unroll
        for (int mt = 0; mt < 4; mt++) {
            int row = b * 128 + wm * 64 + mt * 16 + (l >> 2);
#pragma unroll
            for (int nj = 0; nj < 8; nj++) {
                int col = wn * 64 + nj * 8 + 2 * (l & 3);
                size_t idx0 = ((size_t)ks * ROWS + row) * 128 + col;
                *(float2*)(g_partial + idx0)            = make_float2(acc[mt][nj][0], acc[mt][nj][1]);
                *(float2*)(g_partial + idx0 + 8 * 128)  = make_float2(acc[mt][nj][2], acc[mt][nj][3]);
            }
        }
    } else {
        // =================== producer warps (4-7) ============================
        const int p = t - 128;                 // 0..127 : A row (channel), B row (n)
        const uint32_t rowA = (uint32_t)p * 128u;
        const uint32_t rowB = (uint32_t)p * 128u + TILE_B;
        const int xp7 = (p & 7) * 16;

        const float2* xg = (const float2*)x + (size_t)b * 524288u
                                            + (size_t)ks * 131072u + p;
        const float* wbase = (p < 64) ? (Wm + (size_t)p * 8192u)
                                      : (Wn + (size_t)(p - 64) * 8192u);
        const float4* wq = (const float4*)(wbase + ks * 2048);

        float2 xs[16]; float4 ws[8];

        // prologue: stage chunk0, fill buffer0, stage chunk1
#pragma unroll
        for (int i = 0; i < 16; i++) xs[i] = xg[(size_t)i * 128u];
#pragma unroll
        for (int j = 0; j < 8; j++) ws[j] = wq[j];

        for (int c = -1; c < NCHUNK; c++) {
            if (c + 1 < NCHUNK) {
                // convert staged chunk (c+1) and store into buffer (c+1)&1
                char* sb = smem + ((c + 1) & 1) * STAGE_B;
                uint32_t ah[16], al[16], wh[16], wl[16];
#pragma unroll
                for (int q = 0; q < 16; q++) split2(xs[q].x, xs[q].y, ah[q], al[q]);
#pragma unroll
                for (int j = 0; j < 8; j++) {
                    split2(ws[j].x, ws[j].y, wh[2 * j],     wl[2 * j]);
                    split2(ws[j].z, ws[j].w, wh[2 * j + 1], wl[2 * j + 1]);
                }
#pragma unroll
                for (int j = 0; j < 4; j++) {
                    *(uint4*)(sb + rowA + ((j * 16)      ^ xp7)) =
                        make_uint4(ah[4*j], ah[4*j+1], ah[4*j+2], ah[4*j+3]);
                    *(uint4*)(sb + rowA + ((64 + j * 16) ^ xp7)) =
                        make_uint4(al[4*j], al[4*j+1], al[4*j+2], al[4*j+3]);
                    *(uint4*)(sb + rowB + ((j * 16)      ^ xp7)) =
                        make_uint4(wh[4*j], wh[4*j+1], wh[4*j+2], wh[4*j+3]);
                    *(uint4*)(sb + rowB + ((64 + j * 16) ^ xp7)) =
                        make_uint4(wl[4*j], wl[4*j+1], wl[4*j+2], wl[4*j+3]);
                }
                // stage chunk c+2
                if (c + 2 < NCHUNK) {
                    const float2* xc = xg + (size_t)(c + 2) * 2048u;
#pragma unroll
                    for (int i = 0; i < 16; i++) xs[i] = xc[(size_t)i * 128u];
#pragma unroll
                    for (int j = 0; j < 8; j++) ws[j] = wq[(c + 2) * 8 + j];
                }
            }
            __syncthreads();
        }
    }
}

// ---------------------------------------------------------------------------
// Stage 2: warp per row. lanes 0-15: main experts 4l..4l+3; 16-31: noise.
// ---------------------------------------------------------------------------
__device__ __forceinline__ float softplus_f(float v) {
    return fmaxf(v, 0.0f) + log1pf(expf(-fabsf(v)));
}

__global__ void __launch_bounds__(256) gate_epilogue_kernel(
    const float* __restrict__ bm,
    const float* __restrict__ bn,
    float* __restrict__ out)
{
    const int row  = blockIdx.x * 8 + (threadIdx.x >> 5);
    const int lane = threadIdx.x & 31;

    const float4* pg = (const float4*)g_partial + (size_t)row * 32 + lane;
    float4 s = make_float4(0.f, 0.f, 0.f, 0.f);
#pragma unroll
    for (int ks = 0; ks < KSPLIT; ks++) {
        float4 v = pg[(size_t)ks * ROWS * 32];
        s.x += v.x; s.y += v.y; s.z += v.z; s.w += v.w;
    }

    if (lane < 16) {
        float4 bb = ((const float4*)bm)[lane];
        s.x += bb.x; s.y += bb.y; s.z += bb.z; s.w += bb.w;
    } else {
        float4 bb = ((const float4*)bn)[lane - 16];
        s.x = softplus_f(s.x + bb.x);
        s.y = softplus_f(s.y + bb.y);
        s.z = softplus_f(s.z + bb.z);
        s.w = softplus_f(s.w + bb.w);
    }
    // bring noise (lanes 16-31) down to main lanes (0-15)
    float n0 = __shfl_down_sync(0xffffffffu, s.x, 16);
    float n1 = __shfl_down_sync(0xffffffffu, s.y, 16);
    float n2 = __shfl_down_sync(0xffffffffu, s.z, 16);
    float n3 = __shfl_down_sync(0xffffffffu, s.w, 16);

    float g[4] = { s.x + n0, s.y + n1, s.z + n2, s.w + n3 };

    // local top-2 among 4 (valid on lanes 0-15)
    float v1 = -3.0e38f, v2 = -3.0e38f; int i1 = -1, i2 = -1;
#pragma unroll
    for (int j = 0; j < 4; j++) {
        int idx = 4 * lane + j;
        if (g[j] > v1) { v2 = v1; i2 = i1; v1 = g[j]; i1 = idx; }
        else if (g[j] > v2) { v2 = g[j]; i2 = idx; }
    }
#pragma unroll
    for (int m = 8; m; m >>= 1) {
        float ov1 = __shfl_xor_sync(0xffffffffu, v1, m);
        int   oi1 = __shfl_xor_sync(0xffffffffu, i1, m);
        float ov2 = __shfl_xor_sync(0xffffffffu, v2, m);
        int   oi2 = __shfl_xor_sync(0xffffffffu, i2, m);
        if (ov1 > v1) {
            float c2 = (v1 > ov2) ? v1 : ov2;
            int   ci2 = (v1 > ov2) ? i1 : oi2;
            v1 = ov1; i1 = oi1; v2 = c2; i2 = ci2;
        } else {
            if (ov1 > v2) { v2 = ov1; i2 = oi1; }
        }
    }

    if (lane < 16) {
        float ed = expf(v2 - v1);
        float p1 = 1.0f / (1.0f + ed);
        float p2 = ed / (1.0f + ed);
        float4 o;
        int idx = 4 * lane;
        o.x = (idx     == i1) ? p1 : (idx     == i2) ? p2 : 0.0f;
        o.y = (idx + 1 == i1) ? p1 : (idx + 1 == i2) ? p2 : 0.0f;
        o.z = (idx + 2 == i1) ? p1 : (idx + 2 == i2) ? p2 : 0.0f;
        o.w = (idx + 3 == i1) ? p1 : (idx + 3 == i2) ? p2 : 0.0f;
        ((float4*)out)[(size_t)row * 16 + lane] = o;
    }
}

extern "C" void kernel_launch(void* const* d_in, const int* in_sizes, int n_in,
                              void* d_out, int out_size)
{
    (void)in_sizes; (void)n_in; (void)out_size;
    const float* x  = (const float*)d_in[0];
    const float* Wm = (const float*)d_in[1];
    const float* bm = (const float*)d_in[2];
    const float* Wn = (const float*)d_in[3];
    const float* bn = (const float*)d_in[4];
    float* out = (float*)d_out;

    cudaFuncSetAttribute(gate_gemm_hmma,
                         cudaFuncAttributeMaxDynamicSharedMemorySize, SMEM_BYTES);

    dim3 grid(32, KSPLIT);
    gate_gemm_hmma<<<grid, 256, SMEM_BYTES>>>(x, Wm, Wn);
    gate_epilogue_kernel<<<512, 256>>>(bm, bn, out);
}